// round 1
// baseline (speedup 1.0000x reference)
#include <cuda_runtime.h>
#include <math.h>

#define T 8192
#define D 4096
#define E 8
#define KSEL 2
#define SLOTS (T * KSEL)

// Output layout (float32, concatenated in reference-return order)
#define OFF_XG  0
#define OFF_CNT 67108864ll   // 16384*4096
#define OFF_IDX 67108872ll
#define OFF_SC  67125256ll

// Scratch (no allocations allowed -> __device__ globals)
__device__ int   g_exp[SLOTS];
__device__ float g_prob[SLOTS];
__device__ int   g_pos[SLOTS];

// ---------------------------------------------------------------------------
// Kernel A: router scores + top-2 + softmax over the 2 selected scores.
// 256 threads = 8 warps per block; each warp handles 4 tokens.
// grid = T / 32 = 256 blocks.
// ---------------------------------------------------------------------------
__global__ void __launch_bounds__(256) router_scores_kernel(
    const float* __restrict__ x, const float* __restrict__ W)
{
    const int warp = blockIdx.x * (blockDim.x >> 5) + (threadIdx.x >> 5);
    const int lane = threadIdx.x & 31;
    const int t0 = warp * 4;
    if (t0 >= T) return;

    float acc[4][E];
#pragma unroll
    for (int j = 0; j < 4; j++)
#pragma unroll
        for (int e = 0; e < E; e++) acc[j][e] = 0.f;

    const float4* __restrict__ x4 = (const float4*)x;
    const float4* __restrict__ w4 = (const float4*)W;
    const int rs = D / 4;  // 1024 float4 per row

    for (int i = lane; i < rs; i += 32) {
        float4 xv[4];
#pragma unroll
        for (int j = 0; j < 4; j++) xv[j] = x4[(size_t)(t0 + j) * rs + i];
#pragma unroll
        for (int e = 0; e < E; e++) {
            float4 wv = w4[e * rs + i];
#pragma unroll
            for (int j = 0; j < 4; j++) {
                acc[j][e] += xv[j].x * wv.x + xv[j].y * wv.y +
                             xv[j].z * wv.z + xv[j].w * wv.w;
            }
        }
    }

    // full warp tree-reduce each accumulator
#pragma unroll
    for (int off = 16; off > 0; off >>= 1) {
#pragma unroll
        for (int j = 0; j < 4; j++)
#pragma unroll
            for (int e = 0; e < E; e++)
                acc[j][e] += __shfl_xor_sync(0xffffffffu, acc[j][e], off);
    }

    if (lane < 4) {
        const int t = t0 + lane;
        // stable top-2 (first occurrence wins ties, matching jax.lax.top_k)
        float b0 = -3.4e38f, b1 = -3.4e38f;
        int i0 = 0, i1 = 0;
#pragma unroll
        for (int e = 0; e < E; e++) {
            float s = acc[lane][e];
            if (s > b0) { b1 = b0; i1 = i0; b0 = s; i0 = e; }
            else if (s > b1) { b1 = s; i1 = e; }
        }
        // softmax over [b0, b1], b0 >= b1
        float ex = expf(b1 - b0);
        float inv = 1.f / (1.f + ex);
        g_exp[2 * t]     = i0;
        g_exp[2 * t + 1] = i1;
        g_prob[2 * t]     = inv;
        g_prob[2 * t + 1] = ex * inv;
    }
}

// ---------------------------------------------------------------------------
// Kernel B: deterministic per-expert stable ranking (single block scan).
// 1024 threads, each owns 16 consecutive slots. Hillis-Steele inclusive scan
// of per-thread expert histograms, then per-slot rank assembly.
// Also writes counts / scatter_indices / scores_sorted outputs.
// ---------------------------------------------------------------------------
__global__ void __launch_bounds__(1024) rank_kernel(float* __restrict__ out)
{
    __shared__ int sh[E * 1024];  // [e][tid]
    __shared__ int tot[E];
    __shared__ int baseE[E];

    const int tid = threadIdx.x;
    const int sbase = tid * 16;

    int cnt[E];
#pragma unroll
    for (int e = 0; e < E; e++) cnt[e] = 0;

    int le[16];
#pragma unroll
    for (int k = 0; k < 16; k++) {
        int e = g_exp[sbase + k];
        le[k] = e;
        cnt[e]++;
    }
#pragma unroll
    for (int e = 0; e < E; e++) sh[e * 1024 + tid] = cnt[e];
    __syncthreads();

    // Hillis-Steele inclusive scan along tid for all 8 experts
    for (int off = 1; off < 1024; off <<= 1) {
        int v[E];
#pragma unroll
        for (int e = 0; e < E; e++)
            v[e] = (tid >= off) ? sh[e * 1024 + tid - off] : 0;
        __syncthreads();
#pragma unroll
        for (int e = 0; e < E; e++) sh[e * 1024 + tid] += v[e];
        __syncthreads();
    }

    if (tid < E) tot[tid] = sh[tid * 1024 + 1023];
    __syncthreads();
    if (tid == 0) {
        int s = 0;
#pragma unroll
        for (int e = 0; e < E; e++) { baseE[e] = s; s += tot[e]; }
    }
    __syncthreads();

    int off[E];
#pragma unroll
    for (int e = 0; e < E; e++)
        off[e] = baseE[e] + sh[e * 1024 + tid] - cnt[e];  // exclusive prefix

    int run[E];
#pragma unroll
    for (int e = 0; e < E; e++) run[e] = 0;

#pragma unroll
    for (int k = 0; k < 16; k++) {
        int slot = sbase + k;
        int e = le[k];
        int pos = off[e] + run[e];
        run[e]++;
        g_pos[slot] = pos;
        out[OFF_IDX + pos] = (float)(slot >> 1);   // scatter_indices
        out[OFF_SC  + pos] = g_prob[slot];         // scores_sorted
    }

    if (tid < E) out[OFF_CNT + tid] = (float)tot[tid];  // num_tokens_per_expert
}

// ---------------------------------------------------------------------------
// Kernel C: scatter copy — read each token row once, write 2 destination rows.
// One block per token; 256 threads; float4 moves.
// ---------------------------------------------------------------------------
__global__ void __launch_bounds__(256) scatter_kernel(
    const float* __restrict__ x, float* __restrict__ out)
{
    const int t = blockIdx.x;
    const int p0 = g_pos[2 * t];
    const int p1 = g_pos[2 * t + 1];
    const float4* __restrict__ src = (const float4*)x + (size_t)t * 1024;
    float4* __restrict__ d0 = (float4*)(out + OFF_XG) + (size_t)p0 * 1024;
    float4* __restrict__ d1 = (float4*)(out + OFF_XG) + (size_t)p1 * 1024;

#pragma unroll
    for (int i = threadIdx.x; i < 1024; i += 256) {
        float4 v = src[i];
        d0[i] = v;
        d1[i] = v;
    }
}

extern "C" void kernel_launch(void* const* d_in, const int* in_sizes, int n_in,
                              void* d_out, int out_size)
{
    const float* x = (const float*)d_in[0];
    const float* W = (const float*)d_in[1];
    // defensive: identify by size (x = 33554432 elems, W = 32768 elems)
    if (n_in >= 2 && in_sizes[0] == E * D && in_sizes[1] == (int)((size_t)T * D)) {
        const float* tmp = x; x = W; W = tmp;
    }
    float* out = (float*)d_out;

    router_scores_kernel<<<T / 32, 256>>>(x, W);
    rank_kernel<<<1, 1024>>>(out);
    scatter_kernel<<<T, 256>>>(x, out);
}